// round 4
// baseline (speedup 1.0000x reference)
#include <cuda_runtime.h>
#include <math.h>

// ---------------------------------------------------------------------------
// SparseConvNet: 6 partial-conv layers. N=4, H=W=1024.
// Layers: (1,16,11)(16,16,7)(16,16,5)(16,16,3)(16,16,3)(16,1,1)
// Round 4: co-half split + 8 px/thread (halves weight LDS.128 per FFMA2),
//          CH=16 single-chunk k3 layers. FFMA2 inner loop otherwise as R3.
// ---------------------------------------------------------------------------

#define HW   (1024 * 1024)
#define IMW  1024
#define NPIX (4LL * HW)

__device__ float  g_h0[4 * 16 * HW];
__device__ float  g_h1[4 * 16 * HW];
__device__ float  g_m0[4 * HW];
__device__ float  g_m1[4 * HW];
__device__ double g_stats[6 * 32];
__device__ float2 g_affine[6 * 16];

typedef unsigned long long u64;

__device__ __forceinline__ u64 dup2(float v) {
    u64 r;
    asm("mov.b64 %0, {%1, %1};" : "=l"(r) : "f"(v));
    return r;
}
__device__ __forceinline__ void fma2(u64& d, u64 a, u64 b) {
    asm("fma.rn.f32x2 %0, %1, %2, %0;" : "+l"(d) : "l"(a), "l"(b));
}
__device__ __forceinline__ void unpk(float& lo, float& hi, u64 v) {
    asm("mov.b64 {%0, %1}, %2;" : "=f"(lo), "=f"(hi) : "l"(v));
}

__global__ void zero_stats_k() {
    if (threadIdx.x < 6 * 32) g_stats[threadIdx.x] = 0.0;
}

__global__ void affine_k(const double* __restrict__ st,
                         const float* __restrict__ gam,
                         const float* __restrict__ bet,
                         float2* __restrict__ ab, int nch) {
    int c = threadIdx.x;
    if (c >= nch) return;
    double mean = st[c] / (double)NPIX;
    double var  = st[16 + c] / (double)NPIX - mean * mean;
    float inv = rsqrtf((float)var + 1e-5f);
    float a = gam[c] * inv;
    ab[c] = make_float2(a, bet[c] - (float)mean * a);
}

// ---------------------------------------------------------------------------
// Fused partial-conv layer. Output tile 32x16, 128 threads:
//   tx = tid&31 (x), coh = (tid>>5)&1 (co half, 8 ch), tq = tid>>6 (8 rows).
// Each thread: 8 px * 8 co as 4 packed f32x2 channel-pairs * 8 py.
// ---------------------------------------------------------------------------
template <int K, int CIN, int CH, bool AFF>
__global__ void __launch_bounds__(128, 4) conv_k(
    const float* __restrict__ in, long long inNS,
    const float* __restrict__ mk, long long mkNS,
    const float* __restrict__ wG, const float* __restrict__ bias,
    const float2* __restrict__ aff,
    float* __restrict__ outH, float* __restrict__ outM,
    double* __restrict__ stats) {
    constexpr int TX = 32, TY = 16, P = K / 2;
    constexpr int IW = TX + K - 1;           // input tile width
    constexpr int IH = TY + K - 1;           // input tile height
    constexpr int IHP = IH | 1;              // odd column pitch (col-major)
    constexpr int SMN = IH * IW;             // mask tile (row-major)
    constexpr int SXN = CH * IW * IHP;       // staged input (col-major)
    constexpr int SWOFF = ((SMN + SXN + 3) / 4) * 4;   // 16B-aligned
    constexpr int SWN = CH * K * K * 16;     // staged weights

    extern __shared__ float sm[];
    float* sMk = sm;                         // [IH][IW]
    float* sX  = sm + SMN;                   // [CH][IW][IHP]
    float* sW  = sm + SWOFF;                 // [CH][K][K][16co]
    float* sR  = sm + SWOFF + SWN;           // 128 floats reduce buf

    const int tid = threadIdx.x;
    const int n = blockIdx.z;
    const int x0 = blockIdx.x * TX - P;
    const int y0 = blockIdx.y * TY - P;

    // mask tile (zero pad OOB)
    const float* mkn = mk + (long long)n * mkNS;
    for (int i = tid; i < SMN; i += 128) {
        int ly = i / IW, lx = i - ly * IW;
        int gy = y0 + ly, gx = x0 + lx;
        float m = 0.f;
        if ((unsigned)gy < 1024u && (unsigned)gx < 1024u) m = mkn[gy * IMW + gx];
        sMk[i] = m;
    }

    const int tx  = tid & 31;        // x within output tile
    const int coh = (tid >> 5) & 1;  // output-channel half (8 ch)
    const int tq  = tid >> 6;        // row half (8 rows)
    const float* inn = in + (long long)n * inNS;

    u64 acc2[32];                    // [cp(4)][py(8)] co = coh*8 + 2cp(+1)
#pragma unroll
    for (int i = 0; i < 32; i++) acc2[i] = 0ull;

    for (int c0 = 0; c0 < CIN; c0 += CH) {
        __syncthreads();   // protect prior chunk's sX/sW (and mask on iter 0)

        float2 abr[CH];
#pragma unroll
        for (int ci = 0; ci < CH; ci++)
            abr[ci] = AFF ? aff[c0 + ci] : make_float2(1.f, 0.f);

        // stage input chunk: masked (+ BN affine + relu) into col-major sX
        const float* ipc = inn + (long long)c0 * HW;
        for (int i = tid; i < SMN; i += 128) {
            int ly = i / IW, lx = i - ly * IW;
            int gy = y0 + ly, gx = x0 + lx;
            bool ok = (unsigned)gy < 1024u && (unsigned)gx < 1024u;
            float m = sMk[i];
            int so = lx * IHP + ly;
            const float* p = ipc + (long long)gy * IMW + gx;
            float v[CH];
#pragma unroll
            for (int ci = 0; ci < CH; ci++) {
                v[ci] = 0.f;
                if (ok) v[ci] = p[(long long)ci * HW];
            }
#pragma unroll
            for (int ci = 0; ci < CH; ci++) {
                float t = v[ci];
                if (AFF) t = fmaxf(fmaf(t, abr[ci].x, abr[ci].y), 0.f);
                sX[ci * (IW * IHP) + so] = t * m;
            }
        }
        // stage weight chunk: wG[co][ci][dy][dx] -> sW[ci'][dy][dx][co]
        for (int i = tid; i < SWN; i += 128) {
            int co = i & 15;
            int rest = i >> 4;                       // ci'*K*K + dy*K + dx
            sW[i] = wG[co * (CIN * K * K) + c0 * (K * K) + rest];
        }
        __syncthreads();

#pragma unroll 1
        for (int ci = 0; ci < CH; ci++) {
            const float* colbase = sX + ci * (IW * IHP) + tx * IHP + tq * 8;
            const float* wbase = sW + ci * (K * K * 16) + coh * 8;
#pragma unroll 1
            for (int dx = 0; dx < K; dx++) {
                const float* colp = colbase + dx * IHP;
                u64 vv[K + 7];
#pragma unroll
                for (int j = 0; j < K + 7; j++) vv[j] = dup2(colp[j]);
#pragma unroll
                for (int dy = 0; dy < K; dy++) {
                    const ulonglong2* wq =
                        (const ulonglong2*)(wbase + (dy * K + dx) * 16);
                    ulonglong2 wa = wq[0];
                    ulonglong2 wb = wq[1];
#pragma unroll
                    for (int py = 0; py < 8; py++) {
                        u64 v = vv[dy + py];
                        fma2(acc2[0 * 8 + py], v, wa.x);
                        fma2(acc2[1 * 8 + py], v, wa.y);
                        fma2(acc2[2 * 8 + py], v, wb.x);
                        fma2(acc2[3 * 8 + py], v, wb.y);
                    }
                }
            }
        }
    }

    // mask-sum conv + mask maxpool from the smem mask tile (8 rows/thread)
    float s[8], mm[8];
#pragma unroll
    for (int py = 0; py < 8; py++) { s[py] = 0.f; mm[py] = 0.f; }
    {
        const float* mb = sMk + (tq * 8) * IW + tx;
#pragma unroll 1
        for (int dy = 0; dy < K; dy++) {
#pragma unroll
            for (int dx = 0; dx < K; dx++) {
#pragma unroll
                for (int py = 0; py < 8; py++) {
                    float m = mb[(dy + py) * IW + dx];
                    s[py] += m;
                    mm[py] = fmaxf(mm[py], m);
                }
            }
        }
    }
    float inv[8];
#pragma unroll
    for (int py = 0; py < 8; py++) inv[py] = 1.0f / (s[py] + 1e-8f);

    const int gy = blockIdx.y * TY + tq * 8;
    const int gx = blockIdx.x * TX + tx;

    if (coh == 0) {
        float* mo = outM + (long long)n * HW + gy * IMW + gx;
#pragma unroll
        for (int py = 0; py < 8; py++) mo[py * IMW] = mm[py];
    }

    float* ho = outH + ((long long)n * 16 + coh * 8) * HW + gy * IMW + gx;
    const int lane = tid & 31;
    const int warp = tid >> 5;
#pragma unroll
    for (int cp = 0; cp < 4; cp++) {
        int co0 = coh * 8 + 2 * cp;
        float b0 = bias[co0], b1 = bias[co0 + 1];
        float p1a = 0.f, p2a = 0.f, p1b = 0.f, p2b = 0.f;
#pragma unroll
        for (int py = 0; py < 8; py++) {
            float a0, a1;
            unpk(a0, a1, acc2[cp * 8 + py]);
            float y0v = fmaf(a0, inv[py], b0);
            float y1v = fmaf(a1, inv[py], b1);
            ho[(long long)(2 * cp) * HW + py * IMW] = y0v;
            ho[(long long)(2 * cp + 1) * HW + py * IMW] = y1v;
            p1a += y0v; p2a = fmaf(y0v, y0v, p2a);
            p1b += y1v; p2b = fmaf(y1v, y1v, p2b);
        }
#pragma unroll
        for (int o = 16; o; o >>= 1) {
            p1a += __shfl_xor_sync(0xffffffffu, p1a, o);
            p2a += __shfl_xor_sync(0xffffffffu, p2a, o);
            p1b += __shfl_xor_sync(0xffffffffu, p1b, o);
            p2b += __shfl_xor_sync(0xffffffffu, p2b, o);
        }
        if (lane == 0) {
            sR[(co0 * 2 + 0) * 4 + warp] = p1a;
            sR[(co0 * 2 + 1) * 4 + warp] = p2a;
            sR[((co0 + 1) * 2 + 0) * 4 + warp] = p1b;
            sR[((co0 + 1) * 2 + 1) * 4 + warp] = p2b;
        }
    }
    __syncthreads();
    if (tid < 32) {
        int co = tid >> 1, which = tid & 1;
        // co 0-7 owned by warps {0,2} (coh=0); co 8-15 by warps {1,3}
        int w0 = (co >= 8) ? 1 : 0;
        float v = sR[tid * 4 + w0] + sR[tid * 4 + w0 + 2];
        atomicAdd(&stats[which * 16 + co], (double)v);
    }
}

// ---------------------------------------------------------------------------
// Layer 6: 1x1 partial conv, 16 -> 1 channel.
// ---------------------------------------------------------------------------
__global__ void conv1x1_k(const float* __restrict__ h,
                          const float* __restrict__ mk,
                          const float* __restrict__ w6,
                          const float* __restrict__ b6,
                          const float2* __restrict__ aff,
                          float* __restrict__ y,
                          double* __restrict__ stats) {
    __shared__ float swv[16];
    __shared__ float2 sab[16];
    __shared__ float r1[8], r2[8];
    if (threadIdx.x < 16) {
        swv[threadIdx.x] = w6[threadIdx.x];
        sab[threadIdx.x] = aff[threadIdx.x];
    }
    __syncthreads();
    float bb = b6[0];
    float p1 = 0.f, p2 = 0.f;
    for (long long i = (long long)blockIdx.x * blockDim.x + threadIdx.x;
         i < 4LL * HW; i += (long long)gridDim.x * blockDim.x) {
        long long n = i >> 20;
        long long p = i & (HW - 1);
        float m = mk[i];
        float accv = 0.f;
#pragma unroll
        for (int c = 0; c < 16; c++) {
            float v = h[(n * 16 + c) * HW + p];
            float2 ab = sab[c];
            v = fmaxf(fmaf(v, ab.x, ab.y), 0.f);
            accv = fmaf(swv[c], v, accv);
        }
        float r = 1.0f / (m + 1e-8f);
        float yv = fmaf(accv * m, r, bb);
        y[i] = yv;
        p1 += yv;
        p2 = fmaf(yv, yv, p2);
    }
#pragma unroll
    for (int o = 16; o; o >>= 1) {
        p1 += __shfl_xor_sync(0xffffffffu, p1, o);
        p2 += __shfl_xor_sync(0xffffffffu, p2, o);
    }
    int warp = threadIdx.x >> 5, lane = threadIdx.x & 31;
    if (lane == 0) { r1[warp] = p1; r2[warp] = p2; }
    __syncthreads();
    if (threadIdx.x == 0) {
        float a = 0.f, b = 0.f;
        for (int w = 0; w < (int)(blockDim.x >> 5); w++) { a += r1[w]; b += r2[w]; }
        atomicAdd(&stats[0], (double)a);
        atomicAdd(&stats[16], (double)b);
    }
}

__global__ void final_k(const float* __restrict__ y,
                        const float2* __restrict__ ab,
                        float* __restrict__ o) {
    float2 t = ab[0];
    for (long long i = (long long)blockIdx.x * blockDim.x + threadIdx.x;
         i < 4LL * HW; i += (long long)gridDim.x * blockDim.x)
        o[i] = fmaf(y[i], t.x, t.y);
}

// ---------------------------------------------------------------------------
static constexpr int smem_bytes(int K, int CH) {
    int IW = 32 + K - 1, IH = 16 + K - 1;
    int IHP = IH | 1;
    int smn = IH * IW;
    int sxn = CH * IW * IHP;
    int swoff = ((smn + sxn + 3) / 4) * 4;
    return (swoff + CH * K * K * 16 + 128) * 4;
}

extern "C" void kernel_launch(void* const* d_in, const int* in_sizes, int n_in,
                              void* d_out, int out_size) {
    (void)in_sizes; (void)n_in; (void)out_size;
    const float* x = (const float*)d_in[0];
    const float *wp[6], *bp[6], *gp[6], *btp[6];
    for (int i = 0; i < 6; i++) {
        wp[i]  = (const float*)d_in[1 + 4 * i];
        bp[i]  = (const float*)d_in[2 + 4 * i];
        gp[i]  = (const float*)d_in[3 + 4 * i];
        btp[i] = (const float*)d_in[4 + 4 * i];
    }

    float *h0, *h1, *m0, *m1;
    double* st;
    float2* ab;
    cudaGetSymbolAddress((void**)&h0, g_h0);
    cudaGetSymbolAddress((void**)&h1, g_h1);
    cudaGetSymbolAddress((void**)&m0, g_m0);
    cudaGetSymbolAddress((void**)&m1, g_m1);
    cudaGetSymbolAddress((void**)&st, g_stats);
    cudaGetSymbolAddress((void**)&ab, g_affine);

    cudaFuncSetAttribute(conv_k<11, 1, 1, false>, cudaFuncAttributeMaxDynamicSharedMemorySize, smem_bytes(11, 1));
    cudaFuncSetAttribute(conv_k<7, 16, 4, true>,  cudaFuncAttributeMaxDynamicSharedMemorySize, smem_bytes(7, 4));
    cudaFuncSetAttribute(conv_k<5, 16, 8, true>,  cudaFuncAttributeMaxDynamicSharedMemorySize, smem_bytes(5, 8));
    cudaFuncSetAttribute(conv_k<3, 16, 16, true>, cudaFuncAttributeMaxDynamicSharedMemorySize, smem_bytes(3, 16));

    dim3 grid(1024 / 32, 1024 / 16, 4);
    dim3 blk(128);

    zero_stats_k<<<1, 192>>>();

    conv_k<11, 1, 1, false><<<grid, blk, smem_bytes(11, 1)>>>(
        x, 2LL * HW, x + HW, 2LL * HW, wp[0], bp[0], nullptr, h0, m0, st + 0);
    affine_k<<<1, 16>>>(st + 0, gp[0], btp[0], ab + 0, 16);

    conv_k<7, 16, 4, true><<<grid, blk, smem_bytes(7, 4)>>>(
        h0, 16LL * HW, m0, (long long)HW, wp[1], bp[1], ab + 0, h1, m1, st + 32);
    affine_k<<<1, 16>>>(st + 32, gp[1], btp[1], ab + 16, 16);

    conv_k<5, 16, 8, true><<<grid, blk, smem_bytes(5, 8)>>>(
        h1, 16LL * HW, m1, (long long)HW, wp[2], bp[2], ab + 16, h0, m0, st + 64);
    affine_k<<<1, 16>>>(st + 64, gp[2], btp[2], ab + 32, 16);

    conv_k<3, 16, 16, true><<<grid, blk, smem_bytes(3, 16)>>>(
        h0, 16LL * HW, m0, (long long)HW, wp[3], bp[3], ab + 32, h1, m1, st + 96);
    affine_k<<<1, 16>>>(st + 96, gp[3], btp[3], ab + 48, 16);

    conv_k<3, 16, 16, true><<<grid, blk, smem_bytes(3, 16)>>>(
        h1, 16LL * HW, m1, (long long)HW, wp[4], bp[4], ab + 48, h0, m0, st + 128);
    affine_k<<<1, 16>>>(st + 128, gp[4], btp[4], ab + 64, 16);

    conv1x1_k<<<1184, 256>>>(h0, m0, wp[5], bp[5], ab + 64, h1, st + 160);
    affine_k<<<1, 16>>>(st + 160, gp[5], btp[5], ab + 80, 1);

    final_k<<<4096, 256>>>(h1, ab + 80, (float*)d_out);
}